// round 12
// baseline (speedup 1.0000x reference)
#include <cuda_runtime.h>
#include <cuda_bf16.h>

#define THREADS 256
#define TQ 16
#define SLEN 1024
#define DHEAD 64
#define NEGV (-1e9f)
#define INVT 0.125f

// smem word layout (per CTA, 2 CTAs/SM)
#define SCSTR 1036
#define SC_OFF 0                    // 16*1036 = 16576 words
#define KV_OFF 16576                // double-buffered 64-key K/V chunk
#define KV_BUFW 5120                // K: 64*80 = 5120; V: 16*264 = 4224
#define KROW 80
#define VROW 264
#define MSK_OFF 26816
#define SMEM_WORDS 27840
#define SMEM_BYTES (SMEM_WORDS*4)   // 111,360 B

// packed global scratch:
//   K: [0, 4M)      [row*64 + ks*16 + tig*4 + {hi0,hi1,lo0,lo1}]
//   Q: [4M, 8M)     [(row*2+plane)*32 + d2]  (pre-scaled)
//   V: [8M, 12M)    [bh*65536 + ((kb*4+tig)*64 + d)*4 + {hi0,hi1,lo0,lo1}]
__device__ unsigned g_scratch[12582912];
#define GK 0
#define GQ 4194304
#define GV 8388608

__device__ __forceinline__ void mma_bf16(float c[4], const unsigned a[4], unsigned b0, unsigned b1) {
    asm volatile(
      "mma.sync.aligned.m16n8k16.row.col.f32.bf16.bf16.f32 "
      "{%0,%1,%2,%3}, {%4,%5,%6,%7}, {%8,%9}, {%0,%1,%2,%3};\n"
      : "+f"(c[0]), "+f"(c[1]), "+f"(c[2]), "+f"(c[3])
      : "r"(a[0]), "r"(a[1]), "r"(a[2]), "r"(a[3]), "r"(b0), "r"(b1));
}

__device__ __forceinline__ void split2(float x, float y, unsigned& hi, unsigned& lo) {
    __nv_bfloat162 h = __floats2bfloat162_rn(x, y);
    hi = *reinterpret_cast<unsigned*>(&h);
    float2 hf = __bfloat1622float2(h);
    __nv_bfloat162 l = __floats2bfloat162_rn(x - hf.x, y - hf.y);
    lo = *reinterpret_cast<unsigned*>(&l);
}

__device__ __forceinline__ unsigned saddr(const void* p) {
    return (unsigned)__cvta_generic_to_shared(p);
}
#define CP16(dst, src) asm volatile("cp.async.cg.shared.global [%0], [%1], 16;\n" :: "r"(dst), "l"(src))
#define CP_COMMIT()    asm volatile("cp.async.commit_group;\n")
#define CP_WAIT1()     asm volatile("cp.async.wait_group 1;\n")
#define CP_WAIT0()     asm volatile("cp.async.wait_group 0;\n")

// ---------------- prepass: pack Q/K/V ----------------
__global__ __launch_bounds__(256)
void pack_kernel(const float* __restrict__ q, const float* __restrict__ k,
                 const float* __restrict__ v)
{
    unsigned gidx = blockIdx.x * 256 + threadIdx.x;   // 0 .. 4M-1
    unsigned h0, l0, h1, l1;
    if (gidx < 1048576u) {                            // K
        int idx = gidx;
        int row = idx >> 4, ks = (idx >> 2) & 3, tig = idx & 3;
        const float* kr = k + (size_t)row*DHEAD + ks*16 + tig*2;
        float2 t0 = *(const float2*)kr;
        float2 t1 = *(const float2*)(kr + 8);
        split2(t0.x, t0.y, h0, l0);
        split2(t1.x, t1.y, h1, l1);
        *(uint4*)(g_scratch + GK + (size_t)row*64 + ks*16 + tig*4) = make_uint4(h0, h1, l0, l1);
    } else if (gidx < 3145728u) {                     // Q
        int idx = gidx - 1048576u;
        int d2 = idx & 31, row = idx >> 5;
        float2 t = *(const float2*)(q + (size_t)row*DHEAD + d2*2);
        split2(t.x*INVT, t.y*INVT, h0, l0);
        g_scratch[GQ + (size_t)(row*2+0)*32 + d2] = h0;
        g_scratch[GQ + (size_t)(row*2+1)*32 + d2] = l0;
    } else {                                          // V
        int idx = gidx - 3145728u;
        int d = idx & 63, tig = (idx >> 6) & 3, kb = (idx >> 8) & 63, b = idx >> 14;
        const float* base = v + ((size_t)b*SLEN + kb*16 + tig*2)*DHEAD + d;
        split2(base[0],        base[DHEAD],   h0, l0);
        split2(base[8*DHEAD],  base[9*DHEAD], h1, l1);
        *(uint4*)(g_scratch + GV + (size_t)b*65536 + ((kb*4+tig)*64 + d)*4) = make_uint4(h0, h1, l0, l1);
    }
}

// ---------------- main fused attention ----------------
__global__ __launch_bounds__(THREADS, 2)
void attn_kernel(const int* __restrict__ mask,
                 float* __restrict__ out, float* __restrict__ attn)
{
    extern __shared__ float smem[];
    float*    sc  = smem + SC_OFF;
    unsigned* scu = (unsigned*)sc;
    unsigned* kvb = (unsigned*)(smem + KV_OFF);
    int*      msk = (int*)(smem + MSK_OFF);

    const int tid  = threadIdx.x;
    const int wid  = tid >> 5;       // 0..7
    const int lane = tid & 31;
    const int gid  = lane >> 2;
    const int tig  = lane & 3;
    const int bh   = blockIdx.y;
    const int q0   = blockIdx.x * TQ;

    // ---- staging (cp.async 16B), 64-key chunks ----
    auto stageK = [&](int c, int b) {
        const unsigned* srcb = g_scratch + GK + (size_t)(bh*SLEN + c*64)*64;
        unsigned* dstb = kvb + b*KV_BUFW;
        #pragma unroll
        for (int it = tid; it < 1024; it += THREADS) {
            int row = it >> 4, j = it & 15;
            CP16(saddr(dstb + row*KROW + j*4), srcb + row*64 + j*4);
        }
    };
    auto stageV = [&](int c, int b) {
        const unsigned* srcb = g_scratch + GV + (size_t)bh*65536 + (size_t)c*4096;
        unsigned* dstb = kvb + b*KV_BUFW;
        #pragma unroll
        for (int it = tid; it < 1024; it += THREADS) {
            int u = it >> 6, w = it & 63;
            CP16(saddr(dstb + u*VROW + w*4), srcb + u*256 + w*4);
        }
    };

    stageK(0, 0); CP_COMMIT();
    stageK(1, 1); CP_COMMIT();

    const int* mg_ = mask + (size_t)bh*SLEN;
    for (int i = tid; i < SLEN; i += THREADS) msk[i] = mg_[i];

    // ---- Q fragments (rows gid, gid+8 of 16-row tile) ----
    unsigned qa_hi[4][4], qa_lo[4][4];
    {
        int gr0 = bh*SLEN + q0 + gid;
        const unsigned* Qp = g_scratch + GQ;
        #pragma unroll
        for (int ks = 0; ks < 4; ks++) {
            int d2 = ks*8 + tig;
            qa_hi[ks][0] = Qp[(gr0*2+0)*32 + d2];
            qa_hi[ks][1] = Qp[((gr0+8)*2+0)*32 + d2];
            qa_hi[ks][2] = Qp[(gr0*2+0)*32 + d2 + 4];
            qa_hi[ks][3] = Qp[((gr0+8)*2+0)*32 + d2 + 4];
            qa_lo[ks][0] = Qp[(gr0*2+1)*32 + d2];
            qa_lo[ks][1] = Qp[((gr0+8)*2+1)*32 + d2];
            qa_lo[ks][2] = Qp[(gr0*2+1)*32 + d2 + 4];
            qa_lo[ks][3] = Qp[((gr0+8)*2+1)*32 + d2 + 4];
        }
    }

    // ============ QK^T: 16 chunks of 64 keys; warp nk covers 8 keys ============
    const int nk = wid;
    for (int c = 0; c < 16; c++) {
        if (c < 15) { CP_WAIT1(); } else { CP_WAIT0(); }
        __syncthreads();
        const unsigned* kb = kvb + (c & 1)*KV_BUFW;

        float acc[3][4];
        #pragma unroll
        for (int t = 0; t < 3; t++)
            #pragma unroll
            for (int j = 0; j < 4; j++) acc[t][j] = 0.f;

        #pragma unroll
        for (int ks = 0; ks < 4; ks++) {
            uint4 b0 = *(const uint4*)(kb + (nk*8 + gid)*KROW + ks*16 + tig*4);
            mma_bf16(acc[0], qa_hi[ks], b0.x, b0.y);
            mma_bf16(acc[1], qa_lo[ks], b0.x, b0.y);
            mma_bf16(acc[2], qa_hi[ks], b0.z, b0.w);
        }
        {
            int colb = c*64 + nk*8 + 2*tig;
            int m0 = msk[colb], m1 = msk[colb+1];
            float c0 = acc[0][0] + acc[1][0] + acc[2][0];
            float c1 = acc[0][1] + acc[1][1] + acc[2][1];
            float c2 = acc[0][2] + acc[1][2] + acc[2][2];
            float c3 = acc[0][3] + acc[1][3] + acc[2][3];
            *(float2*)(sc + gid*SCSTR + colb)     = make_float2(m0 ? c0 : NEGV, m1 ? c1 : NEGV);
            *(float2*)(sc + (gid+8)*SCSTR + colb) = make_float2(m0 ? c2 : NEGV, m1 ? c3 : NEGV);
        }
        __syncthreads();
        if (c + 2 < 16) { stageK(c + 2, c & 1); CP_COMMIT(); }
    }

    // prefetch V chunks 0,1 — overlaps softmax
    stageV(0, 0); CP_COMMIT();
    stageV(1, 1); CP_COMMIT();

    // ==== softmax (no max pass; masked exp underflows to 0), pack in place ====
    {
        float* ag = attn + ((size_t)bh*SLEN + q0)*SLEN;
        #pragma unroll
        for (int rr = 0; rr < 2; rr++) {
            int r = wid + rr*8;
            float* srow = sc + r*SCSTR;
            float vv[32];
            float su = 0.f;
            #pragma unroll
            for (int i = 0; i < 16; i++) {
                float2 t = *(const float2*)(srow + i*64 + lane*2);
                float e0 = __expf(t.x), e1 = __expf(t.y);
                vv[2*i] = e0; vv[2*i+1] = e1;
                su += e0 + e1;
            }
            #pragma unroll
            for (int o = 16; o >= 1; o >>= 1)
                su += __shfl_xor_sync(0xffffffffu, su, o);
            float rv = 1.f / su;
            unsigned* srowu = (unsigned*)srow;
            #pragma unroll
            for (int i = 0; i < 16; i++) {
                float p0 = vv[2*i]*rv, p1 = vv[2*i+1]*rv;
                *(float2*)(ag + (size_t)r*SLEN + i*64 + lane*2) = make_float2(p0, p1);
                unsigned hi, lo;
                split2(p0, p1, hi, lo);
                int k2 = i*32 + lane;
                srowu[k2]       = hi;
                srowu[512 + k2] = lo;
            }
        }
    }
    __syncthreads();

    // ====== PV: 8 warps = 2 nd(n=32) x 4-way k-split; 16 chunks of 64 keys ======
    const int pv_nd = wid & 1;          // 0..1
    const int pv_ks = wid >> 1;         // 0..3 : k16 step within chunk

    float oA[4][4], oB[4][4];
    #pragma unroll
    for (int j = 0; j < 4; j++)
        #pragma unroll
        for (int t = 0; t < 4; t++) { oA[j][t] = 0.f; oB[j][t] = 0.f; }

    for (int c = 0; c < 16; c++) {
        if (c < 15) { CP_WAIT1(); } else { CP_WAIT0(); }
        __syncthreads();
        const unsigned* vb = kvb + (c & 1)*KV_BUFW;

        int k2 = c*32 + pv_ks*8 + tig;
        const unsigned* ar0 = scu + gid*SCSTR + k2;
        const unsigned* ar1 = scu + (gid+8)*SCSTR + k2;
        unsigned a_hi[4] = { ar0[0], ar1[0], ar0[4], ar1[4] };
        unsigned a_lo[4] = { ar0[512], ar1[512], ar0[516], ar1[516] };
        int u = pv_ks*4 + tig;
        uint4 bb[4];
        #pragma unroll
        for (int j = 0; j < 4; j++)
            bb[j] = *(const uint4*)(vb + u*VROW + (pv_nd*32 + j*8 + gid)*4);
        #pragma unroll
        for (int j = 0; j < 4; j++) mma_bf16(oA[j], a_hi, bb[j].x, bb[j].y);
        #pragma unroll
        for (int j = 0; j < 4; j++) mma_bf16(oB[j], a_hi, bb[j].z, bb[j].w);
        #pragma unroll
        for (int j = 0; j < 4; j++) mma_bf16(oA[j], a_lo, bb[j].x, bb[j].y);

        __syncthreads();
        if (c + 2 < 16) { stageV(c + 2, c & 1); CP_COMMIT(); }
    }

    // ---- k-split reduction through smem (KV buffers now free) ----
    __syncthreads();
    {
        float* part = (float*)kvb;              // [4][16][72] floats
        #pragma unroll
        for (int j = 0; j < 4; j++) {
            int d0 = pv_nd*32 + j*8 + 2*tig;
            *(float2*)(part + (pv_ks*16 + gid    )*72 + d0) =
                make_float2(oA[j][0]+oB[j][0], oA[j][1]+oB[j][1]);
            *(float2*)(part + (pv_ks*16 + gid + 8)*72 + d0) =
                make_float2(oA[j][2]+oB[j][2], oA[j][3]+oB[j][3]);
        }
        __syncthreads();
        int r = tid >> 4, d = (tid & 15) * 4;
        float4 s0 = *(float4*)(part + (0*16 + r)*72 + d);
        float4 s1 = *(float4*)(part + (1*16 + r)*72 + d);
        float4 s2 = *(float4*)(part + (2*16 + r)*72 + d);
        float4 s3 = *(float4*)(part + (3*16 + r)*72 + d);
        float4 o4 = make_float4(s0.x+s1.x+s2.x+s3.x, s0.y+s1.y+s2.y+s3.y,
                                s0.z+s1.z+s2.z+s3.z, s0.w+s1.w+s2.w+s3.w);
        *(float4*)(out + ((size_t)bh*SLEN + q0 + r)*DHEAD + d) = o4;
    }
}

extern "C" void kernel_launch(void* const* d_in, const int* in_sizes, int n_in,
                              void* d_out, int out_size) {
    const float* q    = (const float*)d_in[0];
    const float* k    = (const float*)d_in[1];
    const float* v    = (const float*)d_in[2];
    const int*   mask = (const int*)d_in[3];
    float* out  = (float*)d_out;
    float* attn = out + (size_t)64*1024*64;

    pack_kernel<<<16384, 256>>>(q, k, v);

    cudaFuncSetAttribute(attn_kernel,
                         cudaFuncAttributeMaxDynamicSharedMemorySize, SMEM_BYTES);
    dim3 grid(SLEN/TQ, 64);
    attn_kernel<<<grid, THREADS, SMEM_BYTES>>>(mask, out, attn);
}

// round 17
// speedup vs baseline: 1.1000x; 1.1000x over previous
#include <cuda_runtime.h>
#include <cuda_bf16.h>

#define THREADS 256
#define SLEN 1024
#define DHEAD 64
#define INVT 0.125f

// smem words (per CTA, 2 CTAs/SM)
#define SW_K   0            // 2 bufs x 5120 (64 keys x 80 words)
#define SW_V   10240        // 2 bufs x 4224 (16 u x 264 words)
#define SW_MSK 18688        // 1024 ints
#define SW_RED 19712        // 128 floats (1/rowsum)
#define SMEM_WORDS 19840
#define SMEM_BYTES (SMEM_WORDS*4)   // 79,360 B
#define KROW 80
#define VROW 264

// packed global scratch (identical layouts to R10, proven correct):
//   K: [row*64 + ks*16 + tig*4 + {hi0,hi1,lo0,lo1}]
//   Q: [(row*2+plane)*32 + d2]  (pre-scaled)
//   V: [bh*65536 + ((kb*4+tig)*64 + d)*4 + {hi0,hi1,lo0,lo1}]
__device__ unsigned g_scratch[12582912];
#define GK 0
#define GQ 4194304
#define GV 8388608

__device__ __forceinline__ void mma_bf16(float c[4], const unsigned a[4], unsigned b0, unsigned b1) {
    asm volatile(
      "mma.sync.aligned.m16n8k16.row.col.f32.bf16.bf16.f32 "
      "{%0,%1,%2,%3}, {%4,%5,%6,%7}, {%8,%9}, {%0,%1,%2,%3};\n"
      : "+f"(c[0]), "+f"(c[1]), "+f"(c[2]), "+f"(c[3])
      : "r"(a[0]), "r"(a[1]), "r"(a[2]), "r"(a[3]), "r"(b0), "r"(b1));
}
__device__ __forceinline__ void split2(float x, float y, unsigned& hi, unsigned& lo) {
    __nv_bfloat162 h = __floats2bfloat162_rn(x, y);
    hi = *reinterpret_cast<unsigned*>(&h);
    float2 hf = __bfloat1622float2(h);
    __nv_bfloat162 l = __floats2bfloat162_rn(x - hf.x, y - hf.y);
    lo = *reinterpret_cast<unsigned*>(&l);
}
__device__ __forceinline__ unsigned saddr(const void* p) {
    return (unsigned)__cvta_generic_to_shared(p);
}
#define CP16(dst, src) asm volatile("cp.async.cg.shared.global [%0], [%1], 16;\n" :: "r"(dst), "l"(src))
#define CP_COMMIT()    asm volatile("cp.async.commit_group;\n")
#define CP_WAIT1()     asm volatile("cp.async.wait_group 1;\n")
#define CP_WAIT0()     asm volatile("cp.async.wait_group 0;\n")

// ---------------- prepass: pack Q/K/V (R10 layouts) ----------------
__global__ __launch_bounds__(256)
void pack_kernel(const float* __restrict__ q, const float* __restrict__ k,
                 const float* __restrict__ v)
{
    unsigned gidx = blockIdx.x * 256 + threadIdx.x;   // 0 .. 4M-1
    unsigned h0, l0, h1, l1;
    if (gidx < 1048576u) {                            // K
        int idx = gidx;
        int row = idx >> 4, ks = (idx >> 2) & 3, tig = idx & 3;
        const float* kr = k + (size_t)row*DHEAD + ks*16 + tig*2;
        float2 t0 = *(const float2*)kr;
        float2 t1 = *(const float2*)(kr + 8);
        split2(t0.x, t0.y, h0, l0);
        split2(t1.x, t1.y, h1, l1);
        *(uint4*)(g_scratch + GK + (size_t)row*64 + ks*16 + tig*4) = make_uint4(h0, h1, l0, l1);
    } else if (gidx < 3145728u) {                     // Q (scaled)
        int idx = gidx - 1048576u;
        int d2 = idx & 31, row = idx >> 5;
        float2 t = *(const float2*)(q + (size_t)row*DHEAD + d2*2);
        split2(t.x*INVT, t.y*INVT, h0, l0);
        g_scratch[GQ + (size_t)(row*2+0)*32 + d2] = h0;
        g_scratch[GQ + (size_t)(row*2+1)*32 + d2] = l0;
    } else {                                          // V
        int idx = gidx - 3145728u;
        int d = idx & 63, tig = (idx >> 6) & 3, kb = (idx >> 8) & 63, b = idx >> 14;
        const float* base = v + ((size_t)b*SLEN + kb*16 + tig*2)*DHEAD + d;
        split2(base[0],        base[DHEAD],   h0, l0);
        split2(base[8*DHEAD],  base[9*DHEAD], h1, l1);
        *(uint4*)(g_scratch + GV + (size_t)b*65536 + ((kb*4+tig)*64 + d)*4) = make_uint4(h0, h1, l0, l1);
    }
}

// ---------------- main: two-pass flash attention, register-resident P ----------------
__global__ __launch_bounds__(THREADS, 2)
void attn_kernel(const int* __restrict__ mask,
                 float* __restrict__ out, float* __restrict__ attn)
{
    extern __shared__ float smem[];
    unsigned* kvK = (unsigned*)smem + SW_K;
    unsigned* kvV = (unsigned*)smem + SW_V;
    int*      msk = (int*)smem + SW_MSK;
    float*    red = smem + SW_RED;

    const int tid  = threadIdx.x;
    const int wq   = tid >> 5;       // warp = 16-query group
    const int lane = tid & 31;
    const int gid  = lane >> 2;
    const int tig  = lane & 3;
    const int bh   = blockIdx.y;
    const int q0   = blockIdx.x * 128;

    auto stageK = [&](int c, int b) {
        const unsigned* src = g_scratch + GK + (size_t)(bh*SLEN + c*64)*64;
        unsigned* dst = kvK + b*5120;
        #pragma unroll
        for (int it = tid; it < 1024; it += THREADS) {
            int row = it >> 4, j = it & 15;
            CP16(saddr(dst + row*KROW + j*4), src + row*64 + j*4);
        }
    };
    auto stageV = [&](int c, int b) {
        const unsigned* src = g_scratch + GV + (size_t)bh*65536 + (size_t)c*4096;
        unsigned* dst = kvV + b*4224;
        #pragma unroll
        for (int it = tid; it < 1024; it += THREADS) {
            int u = it >> 6, w = it & 63;
            CP16(saddr(dst + u*VROW + w*4), src + u*256 + w*4);
        }
    };

    stageK(0, 0); CP_COMMIT();
    stageK(1, 1); CP_COMMIT();

    const int* mg_ = mask + (size_t)bh*SLEN;
    for (int i = tid; i < SLEN; i += THREADS) msk[i] = mg_[i];

    // ---- Q fragments (rows r0 = q0 + wq*16 + gid, +8) ----
    unsigned qa_hi[4][4], qa_lo[4][4];
    {
        int gr0 = bh*SLEN + q0 + wq*16 + gid;
        const unsigned* Qp = g_scratch + GQ;
        #pragma unroll
        for (int ks = 0; ks < 4; ks++) {
            int d2 = ks*8 + tig;
            qa_hi[ks][0] = Qp[(gr0*2+0)*32 + d2];
            qa_hi[ks][1] = Qp[((gr0+8)*2+0)*32 + d2];
            qa_hi[ks][2] = Qp[(gr0*2+0)*32 + d2 + 4];
            qa_hi[ks][3] = Qp[((gr0+8)*2+0)*32 + d2 + 4];
            qa_lo[ks][0] = Qp[(gr0*2+1)*32 + d2];
            qa_lo[ks][1] = Qp[((gr0+8)*2+1)*32 + d2];
            qa_lo[ks][2] = Qp[(gr0*2+1)*32 + d2 + 4];
            qa_lo[ks][3] = Qp[((gr0+8)*2+1)*32 + d2 + 4];
        }
    }

    // ================= pass 1: QK -> exp -> rowsums =================
    float rs0 = 0.f, rs1 = 0.f;
    for (int c = 0; c < 16; c++) {
        if (c < 15) { CP_WAIT1(); } else { CP_WAIT0(); }
        __syncthreads();
        const unsigned* kb = kvK + (c & 1)*5120;

        #pragma unroll
        for (int jp = 0; jp < 8; jp += 2) {
            float acc[2][3][4];
            #pragma unroll
            for (int t = 0; t < 2; t++)
                #pragma unroll
                for (int m = 0; m < 3; m++)
                    #pragma unroll
                    for (int j = 0; j < 4; j++) acc[t][m][j] = 0.f;
            #pragma unroll
            for (int ks = 0; ks < 4; ks++) {
                uint4 b0 = *(const uint4*)(kb + (jp*8 + gid)*KROW + ks*16 + tig*4);
                uint4 b1 = *(const uint4*)(kb + (jp*8 + 8 + gid)*KROW + ks*16 + tig*4);
                mma_bf16(acc[0][0], qa_hi[ks], b0.x, b0.y);
                mma_bf16(acc[1][0], qa_hi[ks], b1.x, b1.y);
                mma_bf16(acc[0][1], qa_lo[ks], b0.x, b0.y);
                mma_bf16(acc[1][1], qa_lo[ks], b1.x, b1.y);
                mma_bf16(acc[0][2], qa_hi[ks], b0.z, b0.w);
                mma_bf16(acc[1][2], qa_hi[ks], b1.z, b1.w);
            }
            #pragma unroll
            for (int t = 0; t < 2; t++) {
                int colb = c*64 + (jp+t)*8 + 2*tig;
                int m0 = msk[colb], m1 = msk[colb+1];
                float s0 = acc[t][0][0] + acc[t][1][0] + acc[t][2][0];
                float s1 = acc[t][0][1] + acc[t][1][1] + acc[t][2][1];
                float s2 = acc[t][0][2] + acc[t][1][2] + acc[t][2][2];
                float s3 = acc[t][0][3] + acc[t][1][3] + acc[t][2][3];
                rs0 += (m0 ? __expf(s0) : 0.f) + (m1 ? __expf(s1) : 0.f);
                rs1 += (m0 ? __expf(s2) : 0.f) + (m1 ? __expf(s3) : 0.f);
            }
        }
        __syncthreads();
        if (c + 2 < 16) { stageK(c + 2, c & 1); CP_COMMIT(); }
    }
    // quad reduce (tig lanes) -> 1/rowsum
    rs0 += __shfl_xor_sync(0xffffffffu, rs0, 1);
    rs0 += __shfl_xor_sync(0xffffffffu, rs0, 2);
    rs1 += __shfl_xor_sync(0xffffffffu, rs1, 1);
    rs1 += __shfl_xor_sync(0xffffffffu, rs1, 2);
    if (tig == 0) {
        red[wq*16 + gid]     = 1.f / rs0;
        red[wq*16 + gid + 8] = 1.f / rs1;
    }
    __syncthreads();

    // ================= pass 2: QK -> attn write + PV =================
    stageK(0, 0); stageV(0, 0); CP_COMMIT();
    stageK(1, 1); stageV(1, 1); CP_COMMIT();
    const float rv0 = red[wq*16 + gid];
    const float rv1 = red[wq*16 + gid + 8];

    float O[8][4];
    #pragma unroll
    for (int j = 0; j < 8; j++)
        #pragma unroll
        for (int t = 0; t < 4; t++) O[j][t] = 0.f;

    float* ag0 = attn + ((size_t)(bh*SLEN + q0 + wq*16 + gid))*SLEN;
    float* ag1 = ag0 + (size_t)8*SLEN;

    for (int c = 0; c < 16; c++) {
        if (c < 15) { CP_WAIT1(); } else { CP_WAIT0(); }
        __syncthreads();
        const unsigned* kb = kvK + (c & 1)*5120;
        const unsigned* vb = kvV + (c & 1)*4224;

        #pragma unroll
        for (int j2 = 0; j2 < 4; j2++) {
            // --- QK for n-tiles 2*j2, 2*j2+1 ---
            float acc[2][3][4];
            #pragma unroll
            for (int t = 0; t < 2; t++)
                #pragma unroll
                for (int m = 0; m < 3; m++)
                    #pragma unroll
                    for (int j = 0; j < 4; j++) acc[t][m][j] = 0.f;
            #pragma unroll
            for (int ks = 0; ks < 4; ks++) {
                uint4 b0 = *(const uint4*)(kb + (j2*16 + gid)*KROW + ks*16 + tig*4);
                uint4 b1 = *(const uint4*)(kb + (j2*16 + 8 + gid)*KROW + ks*16 + tig*4);
                mma_bf16(acc[0][0], qa_hi[ks], b0.x, b0.y);
                mma_bf16(acc[1][0], qa_hi[ks], b1.x, b1.y);
                mma_bf16(acc[0][1], qa_lo[ks], b0.x, b0.y);
                mma_bf16(acc[1][1], qa_lo[ks], b1.x, b1.y);
                mma_bf16(acc[0][2], qa_hi[ks], b0.z, b0.w);
                mma_bf16(acc[1][2], qa_hi[ks], b1.z, b1.w);
            }
            // --- exp + mask, write normalized attn, pack A-frags ---
            float e[2][4];
            #pragma unroll
            for (int t = 0; t < 2; t++) {
                int colb = c*64 + (j2*2+t)*8 + 2*tig;
                int m0 = msk[colb], m1 = msk[colb+1];
                float s0 = acc[t][0][0] + acc[t][1][0] + acc[t][2][0];
                float s1 = acc[t][0][1] + acc[t][1][1] + acc[t][2][1];
                float s2 = acc[t][0][2] + acc[t][1][2] + acc[t][2][2];
                float s3 = acc[t][0][3] + acc[t][1][3] + acc[t][2][3];
                e[t][0] = m0 ? __expf(s0) : 0.f;
                e[t][1] = m1 ? __expf(s1) : 0.f;
                e[t][2] = m0 ? __expf(s2) : 0.f;
                e[t][3] = m1 ? __expf(s3) : 0.f;
                *(float2*)(ag0 + colb) = make_float2(e[t][0]*rv0, e[t][1]*rv0);
                *(float2*)(ag1 + colb) = make_float2(e[t][2]*rv1, e[t][3]*rv1);
            }
            unsigned a_hi[4], a_lo[4];
            split2(e[0][0], e[0][1], a_hi[0], a_lo[0]);
            split2(e[0][2], e[0][3], a_hi[1], a_lo[1]);
            split2(e[1][0], e[1][1], a_hi[2], a_lo[2]);
            split2(e[1][2], e[1][3], a_hi[3], a_lo[3]);

            // --- PV over this k16 group: 8 d-tiles in quads ---
            #pragma unroll
            for (int jq = 0; jq < 8; jq += 4) {
                uint4 bb[4];
                #pragma unroll
                for (int m = 0; m < 4; m++)
                    bb[m] = *(const uint4*)(vb + (j2*4 + tig)*VROW + ((jq+m)*8 + gid)*4);
                #pragma unroll
                for (int m = 0; m < 4; m++) mma_bf16(O[jq+m], a_hi, bb[m].x, bb[m].y);
                #pragma unroll
                for (int m = 0; m < 4; m++) mma_bf16(O[jq+m], a_hi, bb[m].z, bb[m].w);
                #pragma unroll
                for (int m = 0; m < 4; m++) mma_bf16(O[jq+m], a_lo, bb[m].x, bb[m].y);
            }
        }
        __syncthreads();
        if (c + 2 < 16) { stageK(c + 2, c & 1); stageV(c + 2, c & 1); CP_COMMIT(); }
    }

    // ---- store O (normalized) ----
    {
        float* o0 = out + ((size_t)(bh*SLEN + q0 + wq*16 + gid))*DHEAD;
        float* o1 = o0 + 8*DHEAD;
        #pragma unroll
        for (int j = 0; j < 8; j++) {
            int d = j*8 + 2*tig;
            *(float2*)(o0 + d) = make_float2(O[j][0]*rv0, O[j][1]*rv0);
            *(float2*)(o1 + d) = make_float2(O[j][2]*rv1, O[j][3]*rv1);
        }
    }
}

extern "C" void kernel_launch(void* const* d_in, const int* in_sizes, int n_in,
                              void* d_out, int out_size) {
    const float* q    = (const float*)d_in[0];
    const float* k    = (const float*)d_in[1];
    const float* v    = (const float*)d_in[2];
    const int*   mask = (const int*)d_in[3];
    float* out  = (float*)d_out;
    float* attn = out + (size_t)64*1024*64;

    pack_kernel<<<16384, 256>>>(q, k, v);

    cudaFuncSetAttribute(attn_kernel,
                         cudaFuncAttributeMaxDynamicSharedMemorySize, SMEM_BYTES);
    dim3 grid(SLEN/128, 64);
    attn_kernel<<<grid, THREADS, SMEM_BYTES>>>(mask, out, attn);
}